// round 15
// baseline (speedup 1.0000x reference)
#include <cuda_runtime.h>
#include <cuda_bf16.h>
#include <mma.h>
#include <math.h>
#include <cstdint>

using namespace nvcuda;

#define N_NODES 50000
#define N_EDGES 640000
#define N_PAD   50048   // 391 tiles * 128 rows
#define CAP     64      // per-node neighbor bucket capacity (P(deg>=64) ~ e^-61)
// dims: 128 -> 256 -> 128

// ---------------- scratch (device-code-only references; never host args) ----------------
__device__ unsigned g_y1h[N_NODES * 128];    // relu(lin1) bf16 hi plane, packed bf16x2
__device__ unsigned g_y1l[N_NODES * 128];    // residual lo plane
__device__ float    g_z  [N_PAD * 128];      // y1 @ W2^T (pre-agg), f32, padded rows
__device__ int      g_cnt[N_NODES];          // per-node neighbor count (cursor == count)
__device__ int      g_csr2[N_NODES * CAP];   // bucketed src lists
__device__ int      g_idx64;

// bf16 hi/lo split of two floats, packed bf16x2 (x -> low half)
union U32B2 { unsigned u; __nv_bfloat162 b; };
__device__ __forceinline__ void split2(float f0, float f1, unsigned& hi, unsigned& lo) {
    U32B2 h, l;
    h.b = __floats2bfloat162_rn(f0, f1);
    l.b = __floats2bfloat162_rn(f0 - __bfloat162float(h.b.x), f1 - __bfloat162float(h.b.y));
    hi = h.u; lo = l.u;
}

// ---------------- edge index accessor (int32 or int64 storage) ----------------
__device__ __forceinline__ int edge_at(const int* __restrict__ ei, int which, int e) {
    if (g_idx64) return ei[((size_t)which * N_EDGES + (size_t)e) * 2];
    return ei[which * N_EDGES + e];
}

__global__ void k_setup(const int* __restrict__ ei) {
    int i = blockIdx.x * blockDim.x + threadIdx.x;
    if (i < N_NODES) g_cnt[i] = 0;
    if (i == 0) {
        int orr = 0;
#pragma unroll
        for (int j = 0; j < 16; j++) orr |= ei[2 * j + 1];
        g_idx64 = (orr == 0) ? 1 : 0;
    }
}

// ---------------- fill: single pass, direct bucket append ----------------
__global__ void k_fill(const int* __restrict__ ei) {
    int e = blockIdx.x * blockDim.x + threadIdx.x;
    if (e >= N_EDGES) return;
    int s = edge_at(ei, 0, e);
    int d = edge_at(ei, 1, e);
    int off = atomicAdd(&g_cnt[d], 1);
    if (off < CAP) g_csr2[(size_t)d * CAP + off] = s;
}

// ================= lin1 (fused gather): y1 = relu(mean_agg(x) @ W1^T + b1) ==============
// 512 threads (16 warps): warp wid gathers tile rows wid*8..+7 directly into A planes,
// then mg = wid&3 (rows 32*mg..+31), cg = wid>>2 (cols 64*cg..+63) for MMA.
#define L1_LD 136
#define L1_SLD 68
#define L1_WHI 0
#define L1_WLO (256 * L1_LD * 2)
#define L1_A   (2 * 256 * L1_LD * 2)
#define L1_AHI L1_A
#define L1_ALO (L1_A + 128 * L1_LD * 2)
#define L1_SMEM (L1_A + 2 * 128 * L1_LD * 2)    // 208896 bytes
#define L1_TILES ((N_NODES + 127) / 128)        // 391
__global__ void __launch_bounds__(512, 1)
k_lin1_mma(const float4* __restrict__ x, const float* __restrict__ W1,
           const float* __restrict__ b1) {
    extern __shared__ char smem[];
    __nv_bfloat16* Whi = (__nv_bfloat16*)(smem + L1_WHI);
    __nv_bfloat16* Wlo = (__nv_bfloat16*)(smem + L1_WLO);
    __nv_bfloat16* Ahi = (__nv_bfloat16*)(smem + L1_AHI);
    __nv_bfloat16* Alo = (__nv_bfloat16*)(smem + L1_ALO);
    float* stage = (float*)(smem + L1_A);       // [128][68] f32, overlays A planes
    int t = threadIdx.x, wid = t >> 5, lane = t & 31;
    int mg = wid & 3, cg = wid >> 2;

    for (int i = t; i < 256 * 128; i += 512) {
        int n = i >> 7, k = i & 127;
        float w = __ldg(&W1[i]);
        __nv_bfloat16 hb = __float2bfloat16(w);
        Whi[n * L1_LD + k] = hb;
        Wlo[n * L1_LD + k] = __float2bfloat16(w - __bfloat162float(hb));
    }
    __syncthreads();

    for (int tile = blockIdx.x; tile < L1_TILES; tile += gridDim.x) {
        int base = tile * 128;
        // fused gather: warp wid owns rows wid*8 .. wid*8+7 of this tile
#pragma unroll 2
        for (int rr = 0; rr < 8; rr++) {
            int r = wid * 8 + rr;
            int row = base + r;
            float4 acc = make_float4(0.f, 0.f, 0.f, 0.f);
            if (row < N_NODES) {
                acc = __ldg(&x[(size_t)row * 32 + lane]);
                int cnt = min(g_cnt[row], CAP);
                const int* seg = g_csr2 + (size_t)row * CAP;
                for (int i = 0; i < cnt; i += 32) {
                    int lim = cnt - i;
#pragma unroll
                    for (int j = 0; j < 32; j++) {
                        if (j < lim) {
                            int s = __ldg(&seg[i + j]);
                            float4 v = __ldg(&x[(size_t)s * 32 + lane]);
                            acc.x += v.x; acc.y += v.y; acc.z += v.z; acc.w += v.w;
                        }
                    }
                }
                float inv = 1.0f / (float)(cnt + 1);
                acc.x *= inv; acc.y *= inv; acc.z *= inv; acc.w *= inv;
            }
            uint2 hp, lp;
            split2(acc.x, acc.y, hp.x, lp.x);
            split2(acc.z, acc.w, hp.y, lp.y);
            *(uint2*)(Ahi + r * L1_LD + 4 * lane) = hp;
            *(uint2*)(Alo + r * L1_LD + 4 * lane) = lp;
        }
        __syncthreads();

        wmma::fragment<wmma::accumulator, 16, 16, 16, float> acc[2][4];
#pragma unroll
        for (int m = 0; m < 2; m++)
#pragma unroll
            for (int n = 0; n < 4; n++) wmma::fill_fragment(acc[m][n], 0.f);

        int rows0 = mg * 32, cols0 = cg * 64;
#pragma unroll
        for (int ks = 0; ks < 8; ks++) {
            wmma::fragment<wmma::matrix_a, 16, 16, 16, __nv_bfloat16, wmma::row_major> ah[2], al[2];
#pragma unroll
            for (int m = 0; m < 2; m++) {
                wmma::load_matrix_sync(ah[m], Ahi + (rows0 + 16 * m) * L1_LD + ks * 16, L1_LD);
                wmma::load_matrix_sync(al[m], Alo + (rows0 + 16 * m) * L1_LD + ks * 16, L1_LD);
            }
#pragma unroll
            for (int n = 0; n < 4; n++) {
                wmma::fragment<wmma::matrix_b, 16, 16, 16, __nv_bfloat16, wmma::col_major> bh, bl;
                int col = cols0 + 16 * n;
                wmma::load_matrix_sync(bh, Whi + col * L1_LD + ks * 16, L1_LD);
                wmma::load_matrix_sync(bl, Wlo + col * L1_LD + ks * 16, L1_LD);
#pragma unroll
                for (int m = 0; m < 2; m++) {
                    wmma::mma_sync(acc[m][n], ah[m], bh, acc[m][n]);
                    wmma::mma_sync(acc[m][n], ah[m], bl, acc[m][n]);
                    wmma::mma_sync(acc[m][n], al[m], bh, acc[m][n]);
                }
            }
        }

        // epilogue: four 64-col quarters through f32 staging (overlays A region)
#pragma unroll
        for (int h = 0; h < 4; h++) {
            __syncthreads();
            if (cg == h) {
#pragma unroll
                for (int m = 0; m < 2; m++)
#pragma unroll
                    for (int n = 0; n < 4; n++)
                        wmma::store_matrix_sync(stage + (rows0 + 16 * m) * L1_SLD + 16 * n,
                                                acc[m][n], L1_SLD, wmma::mem_row_major);
            }
            __syncthreads();
            for (int i = t; i < 128 * 32; i += 512) {
                int r = i >> 5, p = i & 31, c = 2 * p;
                int row = base + r;
                if (row < N_NODES) {
                    float f0 = fmaxf(stage[r * L1_SLD + c]     + __ldg(&b1[64 * h + c]),     0.f);
                    float f1 = fmaxf(stage[r * L1_SLD + c + 1] + __ldg(&b1[64 * h + c + 1]), 0.f);
                    unsigned hp, lp;
                    split2(f0, f1, hp, lp);
                    g_y1h[(size_t)row * 128 + 32 * h + p] = hp;
                    g_y1l[(size_t)row * 128 + 32 * h + p] = lp;
                }
            }
        }
        __syncthreads();    // staging consumed before next tile's A overwrite
    }
}

// ================= lin2a: z = y1 @ W2^T, 256->128, WMMA bf16 3-split ====================
// 512 threads (16 warps): mg = wid&3 (rows 32*mg..+31), cg = wid>>2 (cols 32*cg..+31).
#define L2_LD 136
#define L2_WLD 264
#define L2_WHI 0
#define L2_WLO (128 * L2_WLD * 2)
#define L2_A   (2 * 128 * L2_WLD * 2)
#define L2_AHI L2_A
#define L2_ALO (L2_A + 128 * L2_LD * 2)
#define L2_SMEM (L2_A + 2 * 128 * L2_LD * 2)    // 204800 bytes
#define L2_TILES ((N_NODES + 127) / 128)        // 391
__global__ void __launch_bounds__(512, 1)
k_lin2_mma(const float* __restrict__ W2) {
    extern __shared__ char smem[];
    __nv_bfloat16* Whi = (__nv_bfloat16*)(smem + L2_WHI);
    __nv_bfloat16* Wlo = (__nv_bfloat16*)(smem + L2_WLO);
    __nv_bfloat16* Ahi = (__nv_bfloat16*)(smem + L2_AHI);
    __nv_bfloat16* Alo = (__nv_bfloat16*)(smem + L2_ALO);
    int t = threadIdx.x, wid = t >> 5;
    int mg = wid & 3, cg = wid >> 2;

    for (int i = t; i < 128 * 256; i += 512) {
        int n = i >> 8, k = i & 255;
        float w = __ldg(&W2[i]);
        __nv_bfloat16 hb = __float2bfloat16(w);
        Whi[n * L2_WLD + k] = hb;
        Wlo[n * L2_WLD + k] = __float2bfloat16(w - __bfloat162float(hb));
    }
    __syncthreads();

    for (int tile = blockIdx.x; tile < L2_TILES; tile += gridDim.x) {
        int base = tile * 128;
        wmma::fragment<wmma::accumulator, 16, 16, 16, float> acc[2][2];
#pragma unroll
        for (int m = 0; m < 2; m++)
#pragma unroll
            for (int n = 0; n < 2; n++) wmma::fill_fragment(acc[m][n], 0.f);

        int rows0 = mg * 32, cols0 = cg * 32;
        for (int kc = 0; kc < 2; kc++) {
            __syncthreads();    // previous chunk readers done
            for (int i = t; i < 128 * 64; i += 512) {   // u32 = bf16x2 pair
                int r = i >> 6, q = i & 63;
                int row = base + r;
                unsigned hp = 0u, lp = 0u;
                if (row < N_NODES) {
                    hp = g_y1h[(size_t)row * 128 + 64 * kc + q];
                    lp = g_y1l[(size_t)row * 128 + 64 * kc + q];
                }
                *(unsigned*)(Ahi + r * L2_LD + 2 * q) = hp;
                *(unsigned*)(Alo + r * L2_LD + 2 * q) = lp;
            }
            __syncthreads();

#pragma unroll
            for (int ks = 0; ks < 8; ks++) {
                wmma::fragment<wmma::matrix_a, 16, 16, 16, __nv_bfloat16, wmma::row_major> ah[2], al[2];
#pragma unroll
                for (int m = 0; m < 2; m++) {
                    wmma::load_matrix_sync(ah[m], Ahi + (rows0 + 16 * m) * L2_LD + ks * 16, L2_LD);
                    wmma::load_matrix_sync(al[m], Alo + (rows0 + 16 * m) * L2_LD + ks * 16, L2_LD);
                }
                int kglob = 128 * kc + 16 * ks;
#pragma unroll
                for (int n = 0; n < 2; n++) {
                    wmma::fragment<wmma::matrix_b, 16, 16, 16, __nv_bfloat16, wmma::col_major> bh, bl;
                    int col = cols0 + 16 * n;
                    wmma::load_matrix_sync(bh, Whi + col * L2_WLD + kglob, L2_WLD);
                    wmma::load_matrix_sync(bl, Wlo + col * L2_WLD + kglob, L2_WLD);
#pragma unroll
                    for (int m = 0; m < 2; m++) {
                        wmma::mma_sync(acc[m][n], ah[m], bh, acc[m][n]);
                        wmma::mma_sync(acc[m][n], ah[m], bl, acc[m][n]);
                        wmma::mma_sync(acc[m][n], al[m], bh, acc[m][n]);
                    }
                }
            }
        }

        // epilogue: straight to padded g_z (rows >= N_NODES land in pad, never read)
#pragma unroll
        for (int m = 0; m < 2; m++)
#pragma unroll
            for (int n = 0; n < 2; n++)
                wmma::store_matrix_sync(g_z + (size_t)(base + rows0 + 16 * m) * 128 + cols0 + 16 * n,
                                        acc[m][n], 128, wmma::mem_row_major);
    }
}

// ---------------- gather2 + final: out = normalize(mean(z) + b2) * exp(ls) ----------------
__global__ void k_gather2f(const float4* __restrict__ b2, const float* __restrict__ logit,
                           float4* __restrict__ out) {
    int gt = blockIdx.x * blockDim.x + threadIdx.x;
    int d = gt >> 5, lane = gt & 31;
    if (d >= N_NODES) return;
    int cnt = min(g_cnt[d], CAP);
    const int* seg = g_csr2 + (size_t)d * CAP;
    const float4* z4 = (const float4*)g_z;
    float4 acc = z4[(size_t)d * 32 + lane];
    for (int i = 0; i < cnt; i += 32) {
        int lim = cnt - i;
#pragma unroll
        for (int j = 0; j < 32; j++) {
            if (j < lim) {
                int s = __ldg(&seg[i + j]);
                float4 v = z4[(size_t)s * 32 + lane];
                acc.x += v.x; acc.y += v.y; acc.z += v.z; acc.w += v.w;
            }
        }
    }
    float invd = 1.0f / (float)(cnt + 1);
    float4 bb = __ldg(&b2[lane]);
    acc.x = acc.x * invd + bb.x;
    acc.y = acc.y * invd + bb.y;
    acc.z = acc.z * invd + bb.z;
    acc.w = acc.w * invd + bb.w;
    float ss = acc.x * acc.x + acc.y * acc.y + acc.z * acc.z + acc.w * acc.w;
#pragma unroll
    for (int off = 16; off > 0; off >>= 1)
        ss += __shfl_xor_sync(0xffffffffu, ss, off);
    float sca = expf(__ldg(logit)) / fmaxf(sqrtf(ss), 1e-12f);
    acc.x *= sca; acc.y *= sca; acc.z *= sca; acc.w *= sca;
    out[(size_t)d * 32 + lane] = acc;
}

// ---------------- launch ----------------
extern "C" void kernel_launch(void* const* d_in, const int* in_sizes, int n_in,
                              void* d_out, int out_size) {
    const void *px = 0, *pei = 0, *pW1 = 0, *pb1 = 0, *pW2 = 0, *pb2 = 0, *pls = 0;
    int nW = 0;
    for (int i = 0; i < n_in; i++) {
        switch (in_sizes[i]) {
            case 6400000: px = d_in[i]; break;
            case 1280000: pei = d_in[i]; break;
            case 32768:   if (nW++ == 0) pW1 = d_in[i]; else pW2 = d_in[i]; break;
            case 256:     pb1 = d_in[i]; break;
            case 128:     pb2 = d_in[i]; break;
            case 1:       pls = d_in[i]; break;
            default: break;
        }
    }
    if (!px)  px  = d_in[0];
    if (!pei) pei = d_in[1];
    if (!pW1) pW1 = d_in[2];
    if (!pb1) pb1 = d_in[3];
    if (!pW2) pW2 = d_in[4];
    if (!pb2) pb2 = d_in[5];
    if (!pls) pls = d_in[6];

    const float4* x  = (const float4*)px;
    const int*    ei = (const int*)pei;
    const float*  W1 = (const float*)pW1;
    const float*  b1 = (const float*)pb1;
    const float*  W2 = (const float*)pW2;
    const float4* b2 = (const float4*)pb2;
    const float*  ls = (const float*)pls;
    float4*       out = (float4*)d_out;

    cudaFuncSetAttribute(k_lin1_mma, cudaFuncAttributeMaxDynamicSharedMemorySize, L1_SMEM);
    cudaFuncSetAttribute(k_lin2_mma, cudaFuncAttributeMaxDynamicSharedMemorySize, L2_SMEM);

    int eblocks = (N_EDGES + 255) / 256;
    int nblocks = (N_NODES + 255) / 256;
    int gblocks = (N_NODES * 32 + 255) / 256;   // warp per node

    k_setup<<<nblocks, 256>>>(ei);
    k_fill<<<eblocks, 256>>>(ei);
    k_lin1_mma<<<148, 512, L1_SMEM>>>(x, W1, b1);
    k_lin2_mma<<<148, 512, L2_SMEM>>>(W2);
    k_gather2f<<<gblocks, 256>>>(b2, ls, out);
}

// round 16
// speedup vs baseline: 1.2194x; 1.2194x over previous
#include <cuda_runtime.h>
#include <cuda_bf16.h>
#include <mma.h>
#include <math.h>
#include <cstdint>

using namespace nvcuda;

#define N_NODES 50000
#define N_EDGES 640000
#define N_PAD   50048   // 391 tiles * 128 rows
#define CAP     64      // per-node bucket capacity (deg ~ Poisson(12.8); P(>=64) ~ e^-61)
// dims: 128 -> 256 -> 128

// ---------------- scratch (device-code-only references; never host args) ----------------
__device__ float4   g_agg1[N_NODES * 32];    // mean-aggregated x (incl self), f32
__device__ unsigned g_y1h[N_NODES * 128];    // relu(lin1) bf16 hi plane, packed bf16x2
__device__ unsigned g_y1l[N_NODES * 128];    // residual lo plane
__device__ float    g_z  [N_PAD * 128];      // y1 @ W2^T (pre-agg), f32, padded rows
__device__ int      g_cnt[N_NODES];          // per-node neighbor count
__device__ int      g_csr2[N_NODES * CAP];   // bucketed src lists
__device__ int      g_idx64;

// bf16 hi/lo split of two floats, packed bf16x2 (x -> low half)
union U32B2 { unsigned u; __nv_bfloat162 b; };
__device__ __forceinline__ void split2(float f0, float f1, unsigned& hi, unsigned& lo) {
    U32B2 h, l;
    h.b = __floats2bfloat162_rn(f0, f1);
    l.b = __floats2bfloat162_rn(f0 - __bfloat162float(h.b.x), f1 - __bfloat162float(h.b.y));
    hi = h.u; lo = l.u;
}

// ---------------- edge index accessor (int32 or int64 storage) ----------------
__device__ __forceinline__ int edge_at(const int* __restrict__ ei, int which, int e) {
    if (g_idx64) return ei[((size_t)which * N_EDGES + (size_t)e) * 2];
    return ei[which * N_EDGES + e];
}

__global__ void k_setup(const int* __restrict__ ei) {
    int i = blockIdx.x * blockDim.x + threadIdx.x;
    if (i < N_NODES) g_cnt[i] = 0;
    if (i == 0) {
        int orr = 0;
#pragma unroll
        for (int j = 0; j < 16; j++) orr |= ei[2 * j + 1];
        g_idx64 = (orr == 0) ? 1 : 0;
    }
}

// ---------------- fill: single pass, direct bucket append ----------------
__global__ void k_fill(const int* __restrict__ ei) {
    int e = blockIdx.x * blockDim.x + threadIdx.x;
    if (e >= N_EDGES) return;
    int s = edge_at(ei, 0, e);
    int d = edge_at(ei, 1, e);
    int off = atomicAdd(&g_cnt[d], 1);
    if (off < CAP) g_csr2[(size_t)d * CAP + off] = s;
}

// ---------------- gather1: agg1[d] = mean(x[d] + sum_{s in N(d)} x[s]) ----------------
__global__ void k_gather1(const float4* __restrict__ x) {
    int gt = blockIdx.x * blockDim.x + threadIdx.x;
    int d = gt >> 5, lane = gt & 31;
    if (d >= N_NODES) return;
    int cnt = min(g_cnt[d], CAP);
    const int* seg = g_csr2 + (size_t)d * CAP;
    float4 acc = __ldg(&x[(size_t)d * 32 + lane]);
    for (int i = 0; i < cnt; i += 32) {
        int lim = cnt - i;
#pragma unroll
        for (int j = 0; j < 32; j++) {
            if (j < lim) {
                int s = __ldg(&seg[i + j]);
                float4 v = __ldg(&x[(size_t)s * 32 + lane]);
                acc.x += v.x; acc.y += v.y; acc.z += v.z; acc.w += v.w;
            }
        }
    }
    float invd = 1.0f / (float)(cnt + 1);
    acc.x *= invd; acc.y *= invd; acc.z *= invd; acc.w *= invd;
    g_agg1[(size_t)d * 32 + lane] = acc;
}

// ================= lin1: y1 = relu(agg1 @ W1^T + b1), 128->256, WMMA bf16 3-split =======
// 512 threads (16 warps): mg = wid&3 (rows 32*mg..+31), cg = wid>>2 (cols 64*cg..+63).
#define L1_LD 136
#define L1_SLD 68
#define L1_WHI 0
#define L1_WLO (256 * L1_LD * 2)
#define L1_A   (2 * 256 * L1_LD * 2)
#define L1_AHI L1_A
#define L1_ALO (L1_A + 128 * L1_LD * 2)
#define L1_SMEM (L1_A + 2 * 128 * L1_LD * 2)    // 208896 bytes
#define L1_TILES ((N_NODES + 127) / 128)        // 391
__global__ void __launch_bounds__(512, 1)
k_lin1_mma(const float* __restrict__ W1, const float* __restrict__ b1) {
    extern __shared__ char smem[];
    __nv_bfloat16* Whi = (__nv_bfloat16*)(smem + L1_WHI);
    __nv_bfloat16* Wlo = (__nv_bfloat16*)(smem + L1_WLO);
    __nv_bfloat16* Ahi = (__nv_bfloat16*)(smem + L1_AHI);
    __nv_bfloat16* Alo = (__nv_bfloat16*)(smem + L1_ALO);
    float* stage = (float*)(smem + L1_A);       // [128][68] f32, overlays A planes
    int t = threadIdx.x, wid = t >> 5;
    int mg = wid & 3, cg = wid >> 2;

    for (int i = t; i < 256 * 128; i += 512) {
        int n = i >> 7, k = i & 127;
        float w = __ldg(&W1[i]);
        __nv_bfloat16 hb = __float2bfloat16(w);
        Whi[n * L1_LD + k] = hb;
        Wlo[n * L1_LD + k] = __float2bfloat16(w - __bfloat162float(hb));
    }
    __syncthreads();

    for (int tile = blockIdx.x; tile < L1_TILES; tile += gridDim.x) {
        int base = tile * 128;
        for (int i = t; i < 128 * 32; i += 512) {
            int r = i >> 5, k4 = i & 31;
            int row = base + r;
            float4 v = make_float4(0.f, 0.f, 0.f, 0.f);
            if (row < N_NODES) v = g_agg1[(size_t)row * 32 + k4];
            uint2 hp, lp;
            split2(v.x, v.y, hp.x, lp.x);
            split2(v.z, v.w, hp.y, lp.y);
            *(uint2*)(Ahi + r * L1_LD + 4 * k4) = hp;
            *(uint2*)(Alo + r * L1_LD + 4 * k4) = lp;
        }
        __syncthreads();

        wmma::fragment<wmma::accumulator, 16, 16, 16, float> acc[2][4];
#pragma unroll
        for (int m = 0; m < 2; m++)
#pragma unroll
            for (int n = 0; n < 4; n++) wmma::fill_fragment(acc[m][n], 0.f);

        int rows0 = mg * 32, cols0 = cg * 64;
#pragma unroll
        for (int ks = 0; ks < 8; ks++) {
            wmma::fragment<wmma::matrix_a, 16, 16, 16, __nv_bfloat16, wmma::row_major> ah[2], al[2];
#pragma unroll
            for (int m = 0; m < 2; m++) {
                wmma::load_matrix_sync(ah[m], Ahi + (rows0 + 16 * m) * L1_LD + ks * 16, L1_LD);
                wmma::load_matrix_sync(al[m], Alo + (rows0 + 16 * m) * L1_LD + ks * 16, L1_LD);
            }
#pragma unroll
            for (int n = 0; n < 4; n++) {
                wmma::fragment<wmma::matrix_b, 16, 16, 16, __nv_bfloat16, wmma::col_major> bh, bl;
                int col = cols0 + 16 * n;
                wmma::load_matrix_sync(bh, Whi + col * L1_LD + ks * 16, L1_LD);
                wmma::load_matrix_sync(bl, Wlo + col * L1_LD + ks * 16, L1_LD);
#pragma unroll
                for (int m = 0; m < 2; m++) {
                    wmma::mma_sync(acc[m][n], ah[m], bh, acc[m][n]);
                    wmma::mma_sync(acc[m][n], ah[m], bl, acc[m][n]);
                    wmma::mma_sync(acc[m][n], al[m], bh, acc[m][n]);
                }
            }
        }

        // epilogue: four 64-col quarters through f32 staging (overlays A region)
#pragma unroll
        for (int h = 0; h < 4; h++) {
            __syncthreads();
            if (cg == h) {
#pragma unroll
                for (int m = 0; m < 2; m++)
#pragma unroll
                    for (int n = 0; n < 4; n++)
                        wmma::store_matrix_sync(stage + (rows0 + 16 * m) * L1_SLD + 16 * n,
                                                acc[m][n], L1_SLD, wmma::mem_row_major);
            }
            __syncthreads();
            for (int i = t; i < 128 * 32; i += 512) {
                int r = i >> 5, p = i & 31, c = 2 * p;
                int row = base + r;
                if (row < N_NODES) {
                    float f0 = fmaxf(stage[r * L1_SLD + c]     + __ldg(&b1[64 * h + c]),     0.f);
                    float f1 = fmaxf(stage[r * L1_SLD + c + 1] + __ldg(&b1[64 * h + c + 1]), 0.f);
                    unsigned hp, lp;
                    split2(f0, f1, hp, lp);
                    g_y1h[(size_t)row * 128 + 32 * h + p] = hp;
                    g_y1l[(size_t)row * 128 + 32 * h + p] = lp;
                }
            }
        }
        __syncthreads();    // staging consumed before next tile's A-load
    }
}

// ================= lin2a: z = y1 @ W2^T, 256->128, WMMA bf16 3-split ====================
// 512 threads (16 warps): mg = wid&3 (rows 32*mg..+31), cg = wid>>2 (cols 32*cg..+31).
// A-plane loads/stores vectorized uint4 (16B): row stride 272B = 17*16 ✓ aligned.
#define L2_LD 136
#define L2_WLD 264
#define L2_WHI 0
#define L2_WLO (128 * L2_WLD * 2)
#define L2_A   (2 * 128 * L2_WLD * 2)
#define L2_AHI L2_A
#define L2_ALO (L2_A + 128 * L2_LD * 2)
#define L2_SMEM (L2_A + 2 * 128 * L2_LD * 2)    // 204800 bytes
#define L2_TILES ((N_NODES + 127) / 128)        // 391
__global__ void __launch_bounds__(512, 1)
k_lin2_mma(const float* __restrict__ W2) {
    extern __shared__ char smem[];
    __nv_bfloat16* Whi = (__nv_bfloat16*)(smem + L2_WHI);
    __nv_bfloat16* Wlo = (__nv_bfloat16*)(smem + L2_WLO);
    __nv_bfloat16* Ahi = (__nv_bfloat16*)(smem + L2_AHI);
    __nv_bfloat16* Alo = (__nv_bfloat16*)(smem + L2_ALO);
    int t = threadIdx.x, wid = t >> 5;
    int mg = wid & 3, cg = wid >> 2;

    for (int i = t; i < 128 * 256; i += 512) {
        int n = i >> 8, k = i & 255;
        float w = __ldg(&W2[i]);
        __nv_bfloat16 hb = __float2bfloat16(w);
        Whi[n * L2_WLD + k] = hb;
        Wlo[n * L2_WLD + k] = __float2bfloat16(w - __bfloat162float(hb));
    }
    __syncthreads();

    for (int tile = blockIdx.x; tile < L2_TILES; tile += gridDim.x) {
        int base = tile * 128;
        wmma::fragment<wmma::accumulator, 16, 16, 16, float> acc[2][2];
#pragma unroll
        for (int m = 0; m < 2; m++)
#pragma unroll
            for (int n = 0; n < 2; n++) wmma::fill_fragment(acc[m][n], 0.f);

        int rows0 = mg * 32, cols0 = cg * 32;
        for (int kc = 0; kc < 2; kc++) {
            __syncthreads();    // previous chunk readers done
            // vectorized A-plane load: 128 rows x 16 uint4 per chunk, both planes
            for (int i = t; i < 128 * 16; i += 512) {
                int r = i >> 4, q4 = i & 15;
                int row = base + r;
                uint4 hp = make_uint4(0u, 0u, 0u, 0u), lp = hp;
                if (row < N_NODES) {
                    hp = *(const uint4*)&g_y1h[(size_t)row * 128 + 64 * kc + 4 * q4];
                    lp = *(const uint4*)&g_y1l[(size_t)row * 128 + 64 * kc + 4 * q4];
                }
                *(uint4*)(Ahi + r * L2_LD + 8 * q4) = hp;
                *(uint4*)(Alo + r * L2_LD + 8 * q4) = lp;
            }
            __syncthreads();

#pragma unroll
            for (int ks = 0; ks < 8; ks++) {
                wmma::fragment<wmma::matrix_a, 16, 16, 16, __nv_bfloat16, wmma::row_major> ah[2], al[2];
#pragma unroll
                for (int m = 0; m < 2; m++) {
                    wmma::load_matrix_sync(ah[m], Ahi + (rows0 + 16 * m) * L2_LD + ks * 16, L2_LD);
                    wmma::load_matrix_sync(al[m], Alo + (rows0 + 16 * m) * L2_LD + ks * 16, L2_LD);
                }
                int kglob = 128 * kc + 16 * ks;
#pragma unroll
                for (int n = 0; n < 2; n++) {
                    wmma::fragment<wmma::matrix_b, 16, 16, 16, __nv_bfloat16, wmma::col_major> bh, bl;
                    int col = cols0 + 16 * n;
                    wmma::load_matrix_sync(bh, Whi + col * L2_WLD + kglob, L2_WLD);
                    wmma::load_matrix_sync(bl, Wlo + col * L2_WLD + kglob, L2_WLD);
#pragma unroll
                    for (int m = 0; m < 2; m++) {
                        wmma::mma_sync(acc[m][n], ah[m], bh, acc[m][n]);
                        wmma::mma_sync(acc[m][n], ah[m], bl, acc[m][n]);
                        wmma::mma_sync(acc[m][n], al[m], bh, acc[m][n]);
                    }
                }
            }
        }

        // epilogue: straight to padded g_z (rows >= N_NODES land in pad, never read)
#pragma unroll
        for (int m = 0; m < 2; m++)
#pragma unroll
            for (int n = 0; n < 2; n++)
                wmma::store_matrix_sync(g_z + (size_t)(base + rows0 + 16 * m) * 128 + cols0 + 16 * n,
                                        acc[m][n], 128, wmma::mem_row_major);
    }
}

// ---------------- gather2 + final: out = normalize(mean(z) + b2) * exp(ls) ----------------
__global__ void k_gather2f(const float4* __restrict__ b2, const float* __restrict__ logit,
                           float4* __restrict__ out) {
    int gt = blockIdx.x * blockDim.x + threadIdx.x;
    int d = gt >> 5, lane = gt & 31;
    if (d >= N_NODES) return;
    int cnt = min(g_cnt[d], CAP);
    const int* seg = g_csr2 + (size_t)d * CAP;
    const float4* z4 = (const float4*)g_z;
    float4 acc = z4[(size_t)d * 32 + lane];
    for (int i = 0; i < cnt; i += 32) {
        int lim = cnt - i;
#pragma unroll
        for (int j = 0; j < 32; j++) {
            if (j < lim) {
                int s = __ldg(&seg[i + j]);
                float4 v = z4[(size_t)s * 32 + lane];
                acc.x += v.x; acc.y += v.y; acc.z += v.z; acc.w += v.w;
            }
        }
    }
    float invd = 1.0f / (float)(cnt + 1);
    float4 bb = __ldg(&b2[lane]);
    acc.x = acc.x * invd + bb.x;
    acc.y = acc.y * invd + bb.y;
    acc.z = acc.z * invd + bb.z;
    acc.w = acc.w * invd + bb.w;
    float ss = acc.x * acc.x + acc.y * acc.y + acc.z * acc.z + acc.w * acc.w;
#pragma unroll
    for (int off = 16; off > 0; off >>= 1)
        ss += __shfl_xor_sync(0xffffffffu, ss, off);
    float sca = expf(__ldg(logit)) / fmaxf(sqrtf(ss), 1e-12f);
    acc.x *= sca; acc.y *= sca; acc.z *= sca; acc.w *= sca;
    out[(size_t)d * 32 + lane] = acc;
}

// ---------------- launch ----------------
extern "C" void kernel_launch(void* const* d_in, const int* in_sizes, int n_in,
                              void* d_out, int out_size) {
    const void *px = 0, *pei = 0, *pW1 = 0, *pb1 = 0, *pW2 = 0, *pb2 = 0, *pls = 0;
    int nW = 0;
    for (int i = 0; i < n_in; i++) {
        switch (in_sizes[i]) {
            case 6400000: px = d_in[i]; break;
            case 1280000: pei = d_in[i]; break;
            case 32768:   if (nW++ == 0) pW1 = d_in[i]; else pW2 = d_in[i]; break;
            case 256:     pb1 = d_in[i]; break;
            case 128:     pb2 = d_in[i]; break;
            case 1:       pls = d_in[i]; break;
            default: break;
        }
    }
    if (!px)  px  = d_in[0];
    if (!pei) pei = d_in[1];
    if (!pW1) pW1 = d_in[2];
    if (!pb1) pb1 = d_in[3];
    if (!pW2) pW2 = d_in[4];
    if (!pb2) pb2 = d_in[5];
    if (!pls) pls = d_in[6];

    const float4* x  = (const float4*)px;
    const int*    ei = (const int*)pei;
    const float*  W1 = (const float*)pW1;
    const float*  b1 = (const float*)pb1;
    const float*  W2 = (const float*)pW2;
    const float4* b2 = (const float4*)pb2;
    const float*  ls = (const float*)pls;
    float4*       out = (float4*)d_out;

    cudaFuncSetAttribute(k_lin1_mma, cudaFuncAttributeMaxDynamicSharedMemorySize, L1_SMEM);
    cudaFuncSetAttribute(k_lin2_mma, cudaFuncAttributeMaxDynamicSharedMemorySize, L2_SMEM);

    int eblocks = (N_EDGES + 255) / 256;
    int nblocks = (N_NODES + 255) / 256;
    int gblocks = (N_NODES * 32 + 255) / 256;   // warp per node

    k_setup<<<nblocks, 256>>>(ei);
    k_fill<<<eblocks, 256>>>(ei);
    k_gather1<<<gblocks, 256>>>(x);
    k_lin1_mma<<<148, 512, L1_SMEM>>>(W1, b1);
    k_lin2_mma<<<148, 512, L2_SMEM>>>(W2);
    k_gather2f<<<gblocks, 256>>>(b2, ls, out);
}

// round 17
// speedup vs baseline: 1.3130x; 1.0768x over previous
#include <cuda_runtime.h>
#include <cuda_bf16.h>
#include <mma.h>
#include <math.h>
#include <cstdint>

using namespace nvcuda;

#define N_NODES 50000
#define N_EDGES 640000
#define N_PAD   50048   // 391 tiles * 128 rows
#define CAP     64      // per-node bucket capacity (deg ~ Poisson(12.8); P(>=64) ~ e^-61)
// dims: 128 -> 256 -> 128

// ---------------- scratch (device-code-only references; never host args) ----------------
__device__ float4   g_agg1[N_NODES * 32];    // mean-aggregated x (incl self), f32
__device__ float    g_y1f [N_PAD * 256];     // raw lin1 GEMM out (pre-bias/relu), f32
__device__ float    g_z  [N_PAD * 128];      // y1 @ W2^T (pre-agg), f32, padded rows
__device__ int      g_cnt[N_NODES];          // per-node neighbor count
__device__ int      g_csr2[N_NODES * CAP];   // bucketed src lists
__device__ int      g_idx64;

// bf16 hi/lo split of two floats, packed bf16x2 (x -> low half)
union U32B2 { unsigned u; __nv_bfloat162 b; };
__device__ __forceinline__ void split2(float f0, float f1, unsigned& hi, unsigned& lo) {
    U32B2 h, l;
    h.b = __floats2bfloat162_rn(f0, f1);
    l.b = __floats2bfloat162_rn(f0 - __bfloat162float(h.b.x), f1 - __bfloat162float(h.b.y));
    hi = h.u; lo = l.u;
}

// ---------------- edge index accessor (int32 or int64 storage) ----------------
__device__ __forceinline__ int edge_at(const int* __restrict__ ei, int which, int e) {
    if (g_idx64) return ei[((size_t)which * N_EDGES + (size_t)e) * 2];
    return ei[which * N_EDGES + e];
}

__global__ void k_setup(const int* __restrict__ ei) {
    int i = blockIdx.x * blockDim.x + threadIdx.x;
    if (i < N_NODES) g_cnt[i] = 0;
    if (i == 0) {
        int orr = 0;
#pragma unroll
        for (int j = 0; j < 16; j++) orr |= ei[2 * j + 1];
        g_idx64 = (orr == 0) ? 1 : 0;
    }
}

// ---------------- fill: single pass, direct bucket append ----------------
__global__ void k_fill(const int* __restrict__ ei) {
    int e = blockIdx.x * blockDim.x + threadIdx.x;
    if (e >= N_EDGES) return;
    int s = edge_at(ei, 0, e);
    int d = edge_at(ei, 1, e);
    int off = atomicAdd(&g_cnt[d], 1);
    if (off < CAP) g_csr2[(size_t)d * CAP + off] = s;
}

// ---------------- gather1: agg1[d] = mean(x[d] + sum_{s in N(d)} x[s]) ----------------
__global__ void k_gather1(const float4* __restrict__ x) {
    int gt = blockIdx.x * blockDim.x + threadIdx.x;
    int d = gt >> 5, lane = gt & 31;
    if (d >= N_NODES) return;
    int cnt = min(g_cnt[d], CAP);
    const int* seg = g_csr2 + (size_t)d * CAP;
    float4 acc = __ldg(&x[(size_t)d * 32 + lane]);
    for (int i = 0; i < cnt; i += 32) {
        int lim = cnt - i;
#pragma unroll
        for (int j = 0; j < 32; j++) {
            if (j < lim) {
                int s = __ldg(&seg[i + j]);
                float4 v = __ldg(&x[(size_t)s * 32 + lane]);
                acc.x += v.x; acc.y += v.y; acc.z += v.z; acc.w += v.w;
            }
        }
    }
    float invd = 1.0f / (float)(cnt + 1);
    acc.x *= invd; acc.y *= invd; acc.z *= invd; acc.w *= invd;
    g_agg1[(size_t)d * 32 + lane] = acc;
}

// ================= lin1: y1f = agg1 @ W1^T (raw, no bias/relu), 128->256 ================
// 512 threads (16 warps): mg = wid&3 (rows 32*mg..+31), cg = wid>>2 (cols 64*cg..+63).
// Epilogue: fragments -> global g_y1f directly (bias/relu/split deferred to lin2).
#define L1_LD 136
#define L1_WHI 0
#define L1_WLO (256 * L1_LD * 2)
#define L1_A   (2 * 256 * L1_LD * 2)
#define L1_AHI L1_A
#define L1_ALO (L1_A + 128 * L1_LD * 2)
#define L1_SMEM (L1_A + 2 * 128 * L1_LD * 2)    // 208896 bytes
#define L1_TILES ((N_NODES + 127) / 128)        // 391
__global__ void __launch_bounds__(512, 1)
k_lin1_mma(const float* __restrict__ W1) {
    extern __shared__ char smem[];
    __nv_bfloat16* Whi = (__nv_bfloat16*)(smem + L1_WHI);
    __nv_bfloat16* Wlo = (__nv_bfloat16*)(smem + L1_WLO);
    __nv_bfloat16* Ahi = (__nv_bfloat16*)(smem + L1_AHI);
    __nv_bfloat16* Alo = (__nv_bfloat16*)(smem + L1_ALO);
    int t = threadIdx.x, wid = t >> 5;
    int mg = wid & 3, cg = wid >> 2;

    for (int i = t; i < 256 * 128; i += 512) {
        int n = i >> 7, k = i & 127;
        float w = __ldg(&W1[i]);
        __nv_bfloat16 hb = __float2bfloat16(w);
        Whi[n * L1_LD + k] = hb;
        Wlo[n * L1_LD + k] = __float2bfloat16(w - __bfloat162float(hb));
    }
    __syncthreads();

    for (int tile = blockIdx.x; tile < L1_TILES; tile += gridDim.x) {
        int base = tile * 128;
        for (int i = t; i < 128 * 32; i += 512) {
            int r = i >> 5, k4 = i & 31;
            int row = base + r;
            float4 v = make_float4(0.f, 0.f, 0.f, 0.f);
            if (row < N_NODES) v = g_agg1[(size_t)row * 32 + k4];
            uint2 hp, lp;
            split2(v.x, v.y, hp.x, lp.x);
            split2(v.z, v.w, hp.y, lp.y);
            *(uint2*)(Ahi + r * L1_LD + 4 * k4) = hp;
            *(uint2*)(Alo + r * L1_LD + 4 * k4) = lp;
        }
        __syncthreads();

        wmma::fragment<wmma::accumulator, 16, 16, 16, float> acc[2][4];
#pragma unroll
        for (int m = 0; m < 2; m++)
#pragma unroll
            for (int n = 0; n < 4; n++) wmma::fill_fragment(acc[m][n], 0.f);

        int rows0 = mg * 32, cols0 = cg * 64;
#pragma unroll
        for (int ks = 0; ks < 8; ks++) {
            wmma::fragment<wmma::matrix_a, 16, 16, 16, __nv_bfloat16, wmma::row_major> ah[2], al[2];
#pragma unroll
            for (int m = 0; m < 2; m++) {
                wmma::load_matrix_sync(ah[m], Ahi + (rows0 + 16 * m) * L1_LD + ks * 16, L1_LD);
                wmma::load_matrix_sync(al[m], Alo + (rows0 + 16 * m) * L1_LD + ks * 16, L1_LD);
            }
#pragma unroll
            for (int n = 0; n < 4; n++) {
                wmma::fragment<wmma::matrix_b, 16, 16, 16, __nv_bfloat16, wmma::col_major> bh, bl;
                int col = cols0 + 16 * n;
                wmma::load_matrix_sync(bh, Whi + col * L1_LD + ks * 16, L1_LD);
                wmma::load_matrix_sync(bl, Wlo + col * L1_LD + ks * 16, L1_LD);
#pragma unroll
                for (int m = 0; m < 2; m++) {
                    wmma::mma_sync(acc[m][n], ah[m], bh, acc[m][n]);
                    wmma::mma_sync(acc[m][n], ah[m], bl, acc[m][n]);
                    wmma::mma_sync(acc[m][n], al[m], bh, acc[m][n]);
                }
            }
        }

        // epilogue: fragments straight to padded global (no staging, no sync)
#pragma unroll
        for (int m = 0; m < 2; m++)
#pragma unroll
            for (int n = 0; n < 4; n++)
                wmma::store_matrix_sync(g_y1f + (size_t)(base + rows0 + 16 * m) * 256 + cols0 + 16 * n,
                                        acc[m][n], 256, wmma::mem_row_major);
        __syncthreads();    // A-plane reads done before next tile overwrites
    }
}

// ================= lin2a: z = relu(y1f + b1) @ W2^T, 256->128 ===========================
// 512 threads (16 warps): mg = wid&3 (rows 32*mg..+31), cg = wid>>2 (cols 32*cg..+31).
// A-phase: load f32 y1f, apply bias1+relu, bf16-split into smem planes.
#define L2_LD 136
#define L2_WLD 264
#define L2_WHI 0
#define L2_WLO (128 * L2_WLD * 2)
#define L2_A   (2 * 128 * L2_WLD * 2)
#define L2_AHI L2_A
#define L2_ALO (L2_A + 128 * L2_LD * 2)
#define L2_SMEM (L2_A + 2 * 128 * L2_LD * 2)    // 204800 bytes
#define L2_TILES ((N_NODES + 127) / 128)        // 391
__global__ void __launch_bounds__(512, 1)
k_lin2_mma(const float* __restrict__ W2, const float* __restrict__ b1) {
    extern __shared__ char smem[];
    __nv_bfloat16* Whi = (__nv_bfloat16*)(smem + L2_WHI);
    __nv_bfloat16* Wlo = (__nv_bfloat16*)(smem + L2_WLO);
    __nv_bfloat16* Ahi = (__nv_bfloat16*)(smem + L2_AHI);
    __nv_bfloat16* Alo = (__nv_bfloat16*)(smem + L2_ALO);
    int t = threadIdx.x, wid = t >> 5;
    int mg = wid & 3, cg = wid >> 2;

    for (int i = t; i < 128 * 256; i += 512) {
        int n = i >> 8, k = i & 255;
        float w = __ldg(&W2[i]);
        __nv_bfloat16 hb = __float2bfloat16(w);
        Whi[n * L2_WLD + k] = hb;
        Wlo[n * L2_WLD + k] = __float2bfloat16(w - __bfloat162float(hb));
    }
    __syncthreads();

    for (int tile = blockIdx.x; tile < L2_TILES; tile += gridDim.x) {
        int base = tile * 128;
        wmma::fragment<wmma::accumulator, 16, 16, 16, float> acc[2][2];
#pragma unroll
        for (int m = 0; m < 2; m++)
#pragma unroll
            for (int n = 0; n < 2; n++) wmma::fill_fragment(acc[m][n], 0.f);

        int rows0 = mg * 32, cols0 = cg * 32;
        for (int kc = 0; kc < 2; kc++) {
            __syncthreads();    // previous chunk readers done
            // A-phase: f32 y1f -> bias+relu -> bf16 hi/lo planes (128 rows x 32 float4)
            for (int i = t; i < 128 * 32; i += 512) {
                int r = i >> 5, k4 = i & 31;
                int row = base + r;
                int col = 128 * kc + 4 * k4;
                float4 v = make_float4(0.f, 0.f, 0.f, 0.f);
                if (row < N_NODES) {
                    v = *(const float4*)&g_y1f[(size_t)row * 256 + col];
                    float4 bb = *(const float4*)&b1[col];
                    v.x = fmaxf(v.x + bb.x, 0.f);
                    v.y = fmaxf(v.y + bb.y, 0.f);
                    v.z = fmaxf(v.z + bb.z, 0.f);
                    v.w = fmaxf(v.w + bb.w, 0.f);
                }
                uint2 hp, lp;
                split2(v.x, v.y, hp.x, lp.x);
                split2(v.z, v.w, hp.y, lp.y);
                *(uint2*)(Ahi + r * L2_LD + 4 * k4) = hp;
                *(uint2*)(Alo + r * L2_LD + 4 * k4) = lp;
            }
            __syncthreads();

#pragma unroll
            for (int ks = 0; ks < 8; ks++) {
                wmma::fragment<wmma::matrix_a, 16, 16, 16, __nv_bfloat16, wmma::row_major> ah[2], al[2];
#pragma unroll
                for (int m = 0; m < 2; m++) {
                    wmma::load_matrix_sync(ah[m], Ahi + (rows0 + 16 * m) * L2_LD + ks * 16, L2_LD);
                    wmma::load_matrix_sync(al[m], Alo + (rows0 + 16 * m) * L2_LD + ks * 16, L2_LD);
                }
                int kglob = 128 * kc + 16 * ks;
#pragma unroll
                for (int n = 0; n < 2; n++) {
                    wmma::fragment<wmma::matrix_b, 16, 16, 16, __nv_bfloat16, wmma::col_major> bh, bl;
                    int col = cols0 + 16 * n;
                    wmma::load_matrix_sync(bh, Whi + col * L2_WLD + kglob, L2_WLD);
                    wmma::load_matrix_sync(bl, Wlo + col * L2_WLD + kglob, L2_WLD);
#pragma unroll
                    for (int m = 0; m < 2; m++) {
                        wmma::mma_sync(acc[m][n], ah[m], bh, acc[m][n]);
                        wmma::mma_sync(acc[m][n], ah[m], bl, acc[m][n]);
                        wmma::mma_sync(acc[m][n], al[m], bh, acc[m][n]);
                    }
                }
            }
        }

        // epilogue: straight to padded g_z (rows >= N_NODES land in pad, never read)
#pragma unroll
        for (int m = 0; m < 2; m++)
#pragma unroll
            for (int n = 0; n < 2; n++)
                wmma::store_matrix_sync(g_z + (size_t)(base + rows0 + 16 * m) * 128 + cols0 + 16 * n,
                                        acc[m][n], 128, wmma::mem_row_major);
    }
}

// ---------------- gather2 + final: out = normalize(mean(z) + b2) * exp(ls) ----------------
__global__ void k_gather2f(const float4* __restrict__ b2, const float* __restrict__ logit,
                           float4* __restrict__ out) {
    int gt = blockIdx.x * blockDim.x + threadIdx.x;
    int d = gt >> 5, lane = gt & 31;
    if (d >= N_NODES) return;
    int cnt = min(g_cnt[d], CAP);
    const int* seg = g_csr2 + (size_t)d * CAP;
    const float4* z4 = (const float4*)g_z;
    float4 acc = z4[(size_t)d * 32 + lane];
    for (int i = 0; i < cnt; i += 32) {
        int lim = cnt - i;
#pragma unroll
        for (int j = 0; j < 32; j++) {
            if (j < lim) {
                int s = __ldg(&seg[i + j]);
                float4 v = z4[(size_t)s * 32 + lane];
                acc.x += v.x; acc.y += v.y; acc.z += v.z; acc.w += v.w;
            }
        }
    }
    float invd = 1.0f / (float)(cnt + 1);
    float4 bb = __ldg(&b2[lane]);
    acc.x = acc.x * invd + bb.x;
    acc.y = acc.y * invd + bb.y;
    acc.z = acc.z * invd + bb.z;
    acc.w = acc.w * invd + bb.w;
    float ss = acc.x * acc.x + acc.y * acc.y + acc.z * acc.z + acc.w * acc.w;
#pragma unroll
    for (int off = 16; off > 0; off >>= 1)
        ss += __shfl_xor_sync(0xffffffffu, ss, off);
    float sca = expf(__ldg(logit)) / fmaxf(sqrtf(ss), 1e-12f);
    acc.x *= sca; acc.y *= sca; acc.z *= sca; acc.w *= sca;
    out[(size_t)d * 32 + lane] = acc;
}

// ---------------- launch ----------------
extern "C" void kernel_launch(void* const* d_in, const int* in_sizes, int n_in,
                              void* d_out, int out_size) {
    const void *px = 0, *pei = 0, *pW1 = 0, *pb1 = 0, *pW2 = 0, *pb2 = 0, *pls = 0;
    int nW = 0;
    for (int i = 0; i < n_in; i++) {
        switch (in_sizes[i]) {
            case 6400000: px = d_in[i]; break;
            case 1280000: pei = d_in[i]; break;
            case 32768:   if (nW++ == 0) pW1 = d_in[i]; else pW2 = d_in[i]; break;
            case 256:     pb1 = d_in[i]; break;
            case 128:     pb2 = d_in[i]; break;
            case 1:       pls = d_in[i]; break;
            default: break;
        }
    }
    if (!px)  px  = d_in[0];
    if (!pei) pei = d_in[1];
    if (!pW1) pW1 = d_in[2];
    if (!pb1) pb1 = d_in[3];
    if (!pW2) pW2 = d_in[4];
    if (!pb2) pb2 = d_in[5];
    if (!pls) pls = d_in[6];

    const float4* x  = (const float4*)px;
    const int*    ei = (const int*)pei;
    const float*  W1 = (const float*)pW1;
    const float*  b1 = (const float*)pb1;
    const float*  W2 = (const float*)pW2;
    const float4* b2 = (const float4*)pb2;
    const float*  ls = (const float*)pls;
    float4*       out = (float4*)d_out;

    cudaFuncSetAttribute(k_lin1_mma, cudaFuncAttributeMaxDynamicSharedMemorySize, L1_SMEM);
    cudaFuncSetAttribute(k_lin2_mma, cudaFuncAttributeMaxDynamicSharedMemorySize, L2_SMEM);

    int eblocks = (N_EDGES + 255) / 256;
    int nblocks = (N_NODES + 255) / 256;
    int gblocks = (N_NODES * 32 + 255) / 256;   // warp per node

    k_setup<<<nblocks, 256>>>(ei);
    k_fill<<<eblocks, 256>>>(ei);
    k_gather1<<<gblocks, 256>>>(x);
    k_lin1_mma<<<148, 512, L1_SMEM>>>(W1);
    k_lin2_mma<<<148, 512, L2_SMEM>>>(W2, b1);
    k_gather2f<<<gblocks, 256>>>(b2, ls, out);
}